// round 6
// baseline (speedup 1.0000x reference)
#include <cuda_runtime.h>
#include <cuda_fp16.h>
#include <cuda_bf16.h>
#include <math.h>
#include <stdint.h>

#define V 50257
#define D 128
#define B 1024
#define C 10
#define TWO_D 256
#define NB 4                 // batch rows per encoder CTA

// vocab GEMM tiling
#define M_CTA 128
#define N_CTA 128
#define KT 32                              // k per smem stage, HMMA path
#define WS_STRIDE 136                      // half2 units; conflict-free fragment loads
#define WS_BUF (16 * WS_STRIDE)            // 2176 words per stage
#define NCHUNK ((V + N_CTA - 1) / N_CTA)   // 393
// pipe split: chunk % SPLIT_MOD == SPLIT_MOD-1 -> FFMA path, else HMMA path
#define SPLIT_MOD 3

// ---------------- scratch ----------------
__device__ float    g_z[B * D];
__device__ unsigned g_zh2[B * D / 2];      // packed half2 z
__device__ float    g_kl[B];
__device__ float    g_pmax[B * NCHUNK];
__device__ float    g_psum[B * NCHUNK];
__device__ float    g_rowval[B];

__device__ __forceinline__ float softplus_f(float x) {
    return fmaxf(x, 0.f) + log1pf(expf(-fabsf(x)));
}

__device__ __forceinline__ void mma_f16(float c[4],
                                        unsigned a0, unsigned a1, unsigned a2, unsigned a3,
                                        unsigned b0, unsigned b1) {
    asm volatile(
        "mma.sync.aligned.m16n8k16.row.col.f32.f16.f16.f32 "
        "{%0,%1,%2,%3}, {%4,%5,%6,%7}, {%8,%9}, {%0,%1,%2,%3};"
        : "+f"(c[0]), "+f"(c[1]), "+f"(c[2]), "+f"(c[3])
        : "r"(a0), "r"(a1), "r"(a2), "r"(a3), "r"(b0), "r"(b1));
}

// ---------------- kernel 1: encoder (NB=4 rows/CTA) + heads + KL + z ----------------
__global__ void __launch_bounds__(256) encoder_kernel(
    const int* __restrict__ center_id, const int* __restrict__ context_ids,
    const float* __restrict__ epsilon, const float* __restrict__ emb,
    const float* __restrict__ prior_means, const float* __restrict__ prior_vars,
    const float* __restrict__ W_enc, const float* __restrict__ b_enc,
    const float* __restrict__ W_mean, const float* __restrict__ b_mean,
    const float* __restrict__ W_var, const float* __restrict__ b_var)
{
    __shared__ float ce_s[NB][D];
    __shared__ float cx_s[NB][C][D];
    __shared__ float h_s[NB][TWO_D];
    __shared__ float mean_s[NB][D];
    __shared__ float var_s[NB][D];
    __shared__ int   ctx_s[NB][C];
    __shared__ int   cid_s[NB];
    __shared__ float red_s[NB][4];

    const int b0  = blockIdx.x * NB;
    const int tid = threadIdx.x;

    if (tid < NB) cid_s[tid] = center_id[b0 + tid];
    if (tid < NB * C) ctx_s[tid / C][tid % C] = context_ids[b0 * C + tid];
    __syncthreads();
    for (int e = tid; e < NB * D; e += 256) {
        int nb = e >> 7, d = e & 127;
        ce_s[nb][d] = emb[cid_s[nb] * D + d];
    }
    for (int e = tid; e < NB * C * D; e += 256) {
        int nb = e / (C * D), r = e % (C * D);
        int c = r >> 7, d = r & 127;
        cx_s[nb][c][d] = emb[ctx_s[nb][c] * D + d];
    }
    __syncthreads();

    const int j = tid;
    float cepart[NB];
    #pragma unroll
    for (int nb = 0; nb < NB; nb++) cepart[nb] = 0.f;
    #pragma unroll 2
    for (int k = 0; k < D; k++) {
        float w1 = W_enc[k * TWO_D + j];
        #pragma unroll
        for (int nb = 0; nb < NB; nb++)
            cepart[nb] = fmaf(ce_s[nb][k], w1, cepart[nb]);
    }

    float acc[NB][C];
    #pragma unroll
    for (int nb = 0; nb < NB; nb++)
        #pragma unroll
        for (int c = 0; c < C; c++) acc[nb][c] = 0.f;
    for (int k = 0; k < D; k++) {
        float w2 = W_enc[(D + k) * TWO_D + j];
        #pragma unroll
        for (int nb = 0; nb < NB; nb++)
            #pragma unroll
            for (int c = 0; c < C; c++)
                acc[nb][c] = fmaf(cx_s[nb][c][k], w2, acc[nb][c]);
    }
    float be = b_enc[j];
    #pragma unroll
    for (int nb = 0; nb < NB; nb++) {
        float base = cepart[nb] + be;
        float hj = 0.f;
        #pragma unroll
        for (int c = 0; c < C; c++) hj += fmaxf(acc[nb][c] + base, 0.f);
        h_s[nb][j] = hj;
    }
    __syncthreads();

    if (tid < D) {
        int d = tid;
        float m[NB];
        #pragma unroll
        for (int nb = 0; nb < NB; nb++) m[nb] = b_mean[d];
        #pragma unroll 2
        for (int k = 0; k < TWO_D; k++) {
            float wm = W_mean[k * D + d];
            #pragma unroll
            for (int nb = 0; nb < NB; nb++)
                m[nb] = fmaf(h_s[nb][k], wm, m[nb]);
        }
        #pragma unroll
        for (int nb = 0; nb < NB; nb++) mean_s[nb][d] = m[nb];
    } else {
        int d = tid - D;
        float vr[NB];
        #pragma unroll
        for (int nb = 0; nb < NB; nb++) vr[nb] = b_var[d];
        #pragma unroll 2
        for (int k = 0; k < TWO_D; k++) {
            float wv = W_var[k * D + d];
            #pragma unroll
            for (int nb = 0; nb < NB; nb++)
                vr[nb] = fmaf(h_s[nb][k], wv, vr[nb]);
        }
        #pragma unroll
        for (int nb = 0; nb < NB; nb++) var_s[nb][d] = softplus_f(vr[nb]);
    }
    __syncthreads();

    float term[NB];
    #pragma unroll
    for (int nb = 0; nb < NB; nb++) term[nb] = 0.f;
    if (tid < D) {
        int d = tid;
        float eps = epsilon[d];
        #pragma unroll
        for (int nb = 0; nb < NB; nb++) {
            int b = b0 + nb;
            float m = mean_s[nb][d];
            float v = var_s[nb][d];
            float z = m + expf(0.5f * v) * eps;
            g_z[b * D + d] = z;
            float zn = __shfl_down_sync(0xffffffffu, z, 1);
            if (!(d & 1)) {
                __half2 hz = __floats2half2_rn(z, zn);
                g_zh2[(b * D + d) >> 1] = *(unsigned*)&hz;
            }
            float pm = prior_means[cid_s[nb] * D + d];
            float pv = softplus_f(prior_vars[cid_s[nb] * D + d]);
            float diff = pm - m;
            term[nb] = v / pv + diff * diff / pv - 1.f + logf(pv) - logf(v);
        }
    }
    #pragma unroll
    for (int nb = 0; nb < NB; nb++) {
        float t = term[nb];
        #pragma unroll
        for (int o = 16; o; o >>= 1) t += __shfl_xor_sync(0xffffffffu, t, o);
        if (tid < D && (tid & 31) == 0) red_s[nb][tid >> 5] = t;
    }
    __syncthreads();
    if (tid < NB) {
        float s = red_s[tid][0] + red_s[tid][1] + red_s[tid][2] + red_s[tid][3];
        g_kl[b0 + tid] = 0.5f * s;
    }
}

// ---------------- kernel 2: HYBRID vocab GEMM -------------------------------
// chunk % SPLIT_MOD != SPLIT_MOD-1 : fp16 mma.sync path (tensor pipe)
// chunk % SPLIT_MOD == SPLIT_MOD-1 : fp32 SIMT path   (fma pipe)
// Both CTA types co-resident per SM -> both pipes busy concurrently.
__global__ void __launch_bounds__(256) vocab_kernel(
    const float* __restrict__ Wv, const float* __restrict__ bvoc)
{
    __shared__ __align__(16) unsigned sm_u[2 * WS_BUF];   // 17408 B, shared by both paths

    const int tid   = threadIdx.x;
    const int chunk = blockIdx.x;
    const int v0    = chunk * N_CTA;
    const int b0    = blockIdx.y * M_CTA;

    if (chunk % SPLIT_MOD != SPLIT_MOD - 1) {
        // ================= HMMA fp16 path =================
        unsigned* Ws = sm_u;
        const int lane = tid & 31;
        const int w    = tid >> 5;
        const int g    = lane >> 2;
        const int cg   = lane & 3;

        const unsigned* zh0 = g_zh2 + (b0 + w * 16 + g) * (D / 2);
        const unsigned* zh1 = zh0 + 8 * (D / 2);

        const int n_f  = tid & 127;
        const int k2b  = tid >> 7;
        const int vf   = v0 + n_f;
        const bool okf = (vf < V);
        const float* wp = Wv + (okf ? vf : 0);

        float acc[16][4];
        #pragma unroll
        for (int t = 0; t < 16; t++)
            #pragma unroll
            for (int i = 0; i < 4; i++) acc[t][i] = 0.f;

        float plo[8], phi[8];
        #define LOADREGS(K0) do {                                             \
            _Pragma("unroll")                                                 \
            for (int i = 0; i < 8; i++) {                                     \
                int kk = (K0) + 2 * (k2b + 2 * i);                            \
                plo[i] = okf ? wp[kk * V] : 0.f;                              \
                phi[i] = okf ? wp[(kk + 1) * V] : 0.f;                        \
            } } while (0)
        #define STOREREGS(BUF) do {                                           \
            _Pragma("unroll")                                                 \
            for (int i = 0; i < 8; i++) {                                     \
                __half2 hv = __floats2half2_rn(plo[i], phi[i]);               \
                (BUF)[(k2b + 2 * i) * WS_STRIDE + n_f] = *(unsigned*)&hv;     \
            } } while (0)

        LOADREGS(0);
        #pragma unroll
        for (int it = 0; it < 4; it++) {
            unsigned* buf = Ws + (it & 1) * WS_BUF;
            STOREREGS(buf);
            __syncthreads();
            if (it < 3) LOADREGS((it + 1) * KT);

            const int k0 = it * KT;
            #pragma unroll
            for (int ks = 0; ks < KT; ks += 16) {
                const int kh = (k0 + ks) >> 1;
                unsigned a0 = zh0[kh + cg];
                unsigned a1 = zh1[kh + cg];
                unsigned a2 = zh0[kh + cg + 4];
                unsigned a3 = zh1[kh + cg + 4];
                const unsigned* wsb0 = buf + ((ks >> 1) + cg) * WS_STRIDE + g;
                const unsigned* wsb1 = wsb0 + 4 * WS_STRIDE;
                #pragma unroll
                for (int t = 0; t < 16; t++)
                    mma_f16(acc[t], a0, a1, a2, a3, wsb0[t * 8], wsb1[t * 8]);
            }
        }
        #undef LOADREGS
        #undef STOREREGS

        float m0 = -INFINITY, m1 = -INFINITY;
        #pragma unroll
        for (int t = 0; t < 16; t++) {
            int n = t * 8 + 2 * cg;
            bool ok0 = (v0 + n) < V;
            bool ok1 = (v0 + n + 1) < V;
            float bv0 = ok0 ? bvoc[v0 + n] : 0.f;
            float bv1 = ok1 ? bvoc[v0 + n + 1] : 0.f;
            acc[t][0] = ok0 ? acc[t][0] + bv0 : -INFINITY;
            acc[t][1] = ok1 ? acc[t][1] + bv1 : -INFINITY;
            acc[t][2] = ok0 ? acc[t][2] + bv0 : -INFINITY;
            acc[t][3] = ok1 ? acc[t][3] + bv1 : -INFINITY;
            m0 = fmaxf(m0, fmaxf(acc[t][0], acc[t][1]));
            m1 = fmaxf(m1, fmaxf(acc[t][2], acc[t][3]));
        }
        #pragma unroll
        for (int o = 1; o <= 2; o <<= 1) {
            m0 = fmaxf(m0, __shfl_xor_sync(0xffffffffu, m0, o));
            m1 = fmaxf(m1, __shfl_xor_sync(0xffffffffu, m1, o));
        }
        float s0 = 0.f, s1 = 0.f;
        #pragma unroll
        for (int t = 0; t < 16; t++) {
            s0 += __expf(acc[t][0] - m0) + __expf(acc[t][1] - m0);
            s1 += __expf(acc[t][2] - m1) + __expf(acc[t][3] - m1);
        }
        #pragma unroll
        for (int o = 1; o <= 2; o <<= 1) {
            s0 += __shfl_xor_sync(0xffffffffu, s0, o);
            s1 += __shfl_xor_sync(0xffffffffu, s1, o);
        }
        if (cg == 0) {
            int r0 = b0 + w * 16 + g;
            g_pmax[r0 * NCHUNK + chunk] = m0;
            g_psum[r0 * NCHUNK + chunk] = s0;
            g_pmax[(r0 + 8) * NCHUNK + chunk] = m1;
            g_psum[(r0 + 8) * NCHUNK + chunk] = s1;
        }
    } else {
        // ================= FFMA fp32 path =================
        // thread grid 16x16: tx = tid&15 (8 cols each), ty = tid>>4 (8 rows each)
        float* Ws2 = (float*)sm_u;          // [16][128]  (2048 floats)
        float* zs2 = (float*)sm_u + 2048;   // [128][17]  (2176 floats)
        const int tx = tid & 15;
        const int ty = tid >> 4;

        float acc[8][8];
        #pragma unroll
        for (int i = 0; i < 8; i++)
            #pragma unroll
            for (int j = 0; j < 8; j++) acc[i][j] = 0.f;

        for (int k0 = 0; k0 < D; k0 += 16) {
            #pragma unroll
            for (int e = 0; e < 8; e++) {
                int idx = tid + e * 256;              // 0..2047
                int kk = idx >> 7, n = idx & 127;
                int v = v0 + n;
                Ws2[kk * 128 + n] = (v < V) ? Wv[(k0 + kk) * V + v] : 0.f;
                int r = idx >> 4, kz = idx & 15;
                zs2[r * 17 + kz] = g_z[(b0 + r) * D + k0 + kz];
            }
            __syncthreads();
            #pragma unroll
            for (int kk = 0; kk < 16; kk++) {
                float wv[8], av[8];
                *(float4*)&wv[0] = *(const float4*)&Ws2[kk * 128 + tx * 8];
                *(float4*)&wv[4] = *(const float4*)&Ws2[kk * 128 + tx * 8 + 4];
                #pragma unroll
                for (int i = 0; i < 8; i++) av[i] = zs2[(ty * 8 + i) * 17 + kk];
                #pragma unroll
                for (int i = 0; i < 8; i++)
                    #pragma unroll
                    for (int j = 0; j < 8; j++)
                        acc[i][j] = fmaf(av[i], wv[j], acc[i][j]);
            }
            __syncthreads();
        }

        float bv[8];
        bool ok[8];
        #pragma unroll
        for (int j = 0; j < 8; j++) {
            int v = v0 + tx * 8 + j;
            ok[j] = (v < V);
            bv[j] = ok[j] ? bvoc[v] : 0.f;
        }
        #pragma unroll
        for (int i = 0; i < 8; i++) {
            float m = -INFINITY;
            #pragma unroll
            for (int j = 0; j < 8; j++) {
                float l = ok[j] ? acc[i][j] + bv[j] : -INFINITY;
                acc[i][j] = l;
                m = fmaxf(m, l);
            }
            #pragma unroll
            for (int o = 1; o <= 8; o <<= 1)
                m = fmaxf(m, __shfl_xor_sync(0xffffffffu, m, o));
            float s = 0.f;
            #pragma unroll
            for (int j = 0; j < 8; j++) s += __expf(acc[i][j] - m);  // exp(-inf)=0
            #pragma unroll
            for (int o = 1; o <= 8; o <<= 1)
                s += __shfl_xor_sync(0xffffffffu, s, o);
            if (tx == 0) {
                int row = b0 + ty * 8 + i;
                g_pmax[row * NCHUNK + chunk] = m;
                g_psum[row * NCHUNK + chunk] = s;
            }
        }
    }
}

// ---------------- kernel 3: per-row logsumexp combine + context gather ----------------
__global__ void __launch_bounds__(128) finalize_rows(
    const float* __restrict__ Wv, const float* __restrict__ bvoc,
    const int* __restrict__ context_ids)
{
    const int warp = threadIdx.x >> 5;
    const int lane = threadIdx.x & 31;
    const int b = blockIdx.x * 4 + warp;

    float m = -INFINITY, s = 0.f;
    for (int ch = lane; ch < NCHUNK; ch += 32) {
        float m2 = g_pmax[b * NCHUNK + ch];
        float s2 = g_psum[b * NCHUNK + ch];
        if (m2 > m) { s = s * __expf(m - m2) + s2; m = m2; }
        else        { s += s2 * __expf(m2 - m); }
    }
    #pragma unroll
    for (int o = 16; o; o >>= 1) {
        float m2 = __shfl_xor_sync(0xffffffffu, m, o);
        float s2 = __shfl_xor_sync(0xffffffffu, s, o);
        if (m2 > m) { s = s * __expf(m - m2) + s2; m = m2; }
        else        { s += s2 * __expf(m2 - m); }
    }
    float lse = m + logf(s);

    float zr[4];
    #pragma unroll
    for (int t = 0; t < 4; t++) zr[t] = g_z[b * D + lane + 32 * t];

    float rec = 0.f;
    #pragma unroll
    for (int c = 0; c < C; c++) {
        int v = context_ids[b * C + c];
        float p = 0.f;
        #pragma unroll
        for (int t = 0; t < 4; t++)
            p = fmaf(zr[t], Wv[(lane + 32 * t) * V + v], p);
        #pragma unroll
        for (int o = 16; o; o >>= 1) p += __shfl_xor_sync(0xffffffffu, p, o);
        rec += p + bvoc[v] - lse;
    }
    if (lane == 0) g_rowval[b] = rec - g_kl[b];
}

// ---------------- kernel 4: deterministic mean over B ----------------
__global__ void __launch_bounds__(1024) reduce_mean(float* __restrict__ out)
{
    __shared__ float red_s[32];
    const int tid = threadIdx.x;
    float v = g_rowval[tid];
    #pragma unroll
    for (int o = 16; o; o >>= 1) v += __shfl_xor_sync(0xffffffffu, v, o);
    if ((tid & 31) == 0) red_s[tid >> 5] = v;
    __syncthreads();
    if (tid < 32) {
        float sv = red_s[tid];
        #pragma unroll
        for (int o = 16; o; o >>= 1) sv += __shfl_xor_sync(0xffffffffu, sv, o);
        if (tid == 0) out[0] = sv * (1.0f / (float)B);
    }
}

// ---------------- launch ----------------
extern "C" void kernel_launch(void* const* d_in, const int* in_sizes, int n_in,
                              void* d_out, int out_size)
{
    const int*   center_id   = (const int*)d_in[0];
    const int*   context_ids = (const int*)d_in[1];
    const float* epsilon     = (const float*)d_in[2];
    const float* emb         = (const float*)d_in[3];
    const float* prior_means = (const float*)d_in[4];
    const float* prior_vars  = (const float*)d_in[5];
    const float* W_enc       = (const float*)d_in[6];
    const float* b_enc       = (const float*)d_in[7];
    const float* W_mean      = (const float*)d_in[8];
    const float* b_mean      = (const float*)d_in[9];
    const float* W_var       = (const float*)d_in[10];
    const float* b_var       = (const float*)d_in[11];
    const float* W_vocab     = (const float*)d_in[12];
    const float* b_vocab     = (const float*)d_in[13];
    float* out = (float*)d_out;

    encoder_kernel<<<B / NB, 256>>>(center_id, context_ids, epsilon, emb,
                                    prior_means, prior_vars,
                                    W_enc, b_enc, W_mean, b_mean, W_var, b_var);

    dim3 grid2(NCHUNK, B / M_CTA);
    vocab_kernel<<<grid2, 256>>>(W_vocab, b_vocab);

    finalize_rows<<<B / 4, 128>>>(W_vocab, b_vocab, context_ids);

    reduce_mean<<<1, 1024>>>(out);
}

// round 7
// speedup vs baseline: 1.3539x; 1.3539x over previous
#include <cuda_runtime.h>
#include <cuda_fp16.h>
#include <cuda_bf16.h>
#include <math.h>
#include <stdint.h>

#define V 50257
#define D 128
#define B 1024
#define C 10
#define TWO_D 256
#define NB 4                 // batch rows per encoder CTA

// hybrid vocab GEMM tiling: per CTA 128 rows x (96 HMMA cols + 48 FFMA cols)
#define M_CTA 128
#define HN 96                              // tensor-pipe columns
#define FN 48                              // fma-pipe columns
#define NW (HN + FN)                       // 144 cols per chunk
#define NCHUNK ((V + NW - 1) / NW)         // 350
#define KT 32                              // k per smem stage
#define WS2 104                            // half2 stride (104 mod 32 = 8 -> conflict-free)
#define WSBUF (16 * WS2)                   // 1664 u32 per stage
#define WFS 48                             // FFMA W stride (floats)
#define WFBUF (KT * WFS)                   // 1536 floats per stage

// ---------------- scratch ----------------
__device__ float    g_z[B * D];
__device__ float    g_zT[D * B];           // transposed z for FFMA broadcast loads
__device__ unsigned g_zh2[B * D / 2];      // packed half2 z
__device__ float    g_kl[B];
__device__ float    g_pmax[B * NCHUNK];
__device__ float    g_psum[B * NCHUNK];
__device__ float    g_rowval[B];

__device__ __forceinline__ float softplus_f(float x) {
    return fmaxf(x, 0.f) + log1pf(expf(-fabsf(x)));
}

__device__ __forceinline__ void mma_f16(float c[4],
                                        unsigned a0, unsigned a1, unsigned a2, unsigned a3,
                                        unsigned b0, unsigned b1) {
    asm volatile(
        "mma.sync.aligned.m16n8k16.row.col.f32.f16.f16.f32 "
        "{%0,%1,%2,%3}, {%4,%5,%6,%7}, {%8,%9}, {%0,%1,%2,%3};"
        : "+f"(c[0]), "+f"(c[1]), "+f"(c[2]), "+f"(c[3])
        : "r"(a0), "r"(a1), "r"(a2), "r"(a3), "r"(b0), "r"(b1));
}

// ---------------- kernel 1: encoder (NB=4 rows/CTA) + heads + KL + z ----------------
__global__ void __launch_bounds__(256) encoder_kernel(
    const int* __restrict__ center_id, const int* __restrict__ context_ids,
    const float* __restrict__ epsilon, const float* __restrict__ emb,
    const float* __restrict__ prior_means, const float* __restrict__ prior_vars,
    const float* __restrict__ W_enc, const float* __restrict__ b_enc,
    const float* __restrict__ W_mean, const float* __restrict__ b_mean,
    const float* __restrict__ W_var, const float* __restrict__ b_var)
{
    __shared__ float ce_s[NB][D];
    __shared__ float cx_s[NB][C][D];
    __shared__ float h_s[NB][TWO_D];
    __shared__ float mean_s[NB][D];
    __shared__ float var_s[NB][D];
    __shared__ int   ctx_s[NB][C];
    __shared__ int   cid_s[NB];
    __shared__ float red_s[NB][4];

    const int b0  = blockIdx.x * NB;
    const int tid = threadIdx.x;

    if (tid < NB) cid_s[tid] = center_id[b0 + tid];
    if (tid < NB * C) ctx_s[tid / C][tid % C] = context_ids[b0 * C + tid];
    __syncthreads();
    for (int e = tid; e < NB * D; e += 256) {
        int nb = e >> 7, d = e & 127;
        ce_s[nb][d] = emb[cid_s[nb] * D + d];
    }
    for (int e = tid; e < NB * C * D; e += 256) {
        int nb = e / (C * D), r = e % (C * D);
        int c = r >> 7, d = r & 127;
        cx_s[nb][c][d] = emb[ctx_s[nb][c] * D + d];
    }
    __syncthreads();

    const int j = tid;
    float cepart[NB];
    #pragma unroll
    for (int nb = 0; nb < NB; nb++) cepart[nb] = 0.f;
    #pragma unroll 2
    for (int k = 0; k < D; k++) {
        float w1 = W_enc[k * TWO_D + j];
        #pragma unroll
        for (int nb = 0; nb < NB; nb++)
            cepart[nb] = fmaf(ce_s[nb][k], w1, cepart[nb]);
    }

    float acc[NB][C];
    #pragma unroll
    for (int nb = 0; nb < NB; nb++)
        #pragma unroll
        for (int c = 0; c < C; c++) acc[nb][c] = 0.f;
    for (int k = 0; k < D; k++) {
        float w2 = W_enc[(D + k) * TWO_D + j];
        #pragma unroll
        for (int nb = 0; nb < NB; nb++)
            #pragma unroll
            for (int c = 0; c < C; c++)
                acc[nb][c] = fmaf(cx_s[nb][c][k], w2, acc[nb][c]);
    }
    float be = b_enc[j];
    #pragma unroll
    for (int nb = 0; nb < NB; nb++) {
        float base = cepart[nb] + be;
        float hj = 0.f;
        #pragma unroll
        for (int c = 0; c < C; c++) hj += fmaxf(acc[nb][c] + base, 0.f);
        h_s[nb][j] = hj;
    }
    __syncthreads();

    if (tid < D) {
        int d = tid;
        float m[NB];
        #pragma unroll
        for (int nb = 0; nb < NB; nb++) m[nb] = b_mean[d];
        #pragma unroll 2
        for (int k = 0; k < TWO_D; k++) {
            float wm = W_mean[k * D + d];
            #pragma unroll
            for (int nb = 0; nb < NB; nb++)
                m[nb] = fmaf(h_s[nb][k], wm, m[nb]);
        }
        #pragma unroll
        for (int nb = 0; nb < NB; nb++) mean_s[nb][d] = m[nb];
    } else {
        int d = tid - D;
        float vr[NB];
        #pragma unroll
        for (int nb = 0; nb < NB; nb++) vr[nb] = b_var[d];
        #pragma unroll 2
        for (int k = 0; k < TWO_D; k++) {
            float wv = W_var[k * D + d];
            #pragma unroll
            for (int nb = 0; nb < NB; nb++)
                vr[nb] = fmaf(h_s[nb][k], wv, vr[nb]);
        }
        #pragma unroll
        for (int nb = 0; nb < NB; nb++) var_s[nb][d] = softplus_f(vr[nb]);
    }
    __syncthreads();

    float term[NB];
    #pragma unroll
    for (int nb = 0; nb < NB; nb++) term[nb] = 0.f;
    if (tid < D) {
        int d = tid;
        float eps = epsilon[d];
        #pragma unroll
        for (int nb = 0; nb < NB; nb++) {
            int b = b0 + nb;
            float m = mean_s[nb][d];
            float v = var_s[nb][d];
            float z = m + expf(0.5f * v) * eps;
            g_z[b * D + d] = z;
            g_zT[d * B + b] = z;
            float zn = __shfl_down_sync(0xffffffffu, z, 1);
            if (!(d & 1)) {
                __half2 hz = __floats2half2_rn(z, zn);
                g_zh2[(b * D + d) >> 1] = *(unsigned*)&hz;
            }
            float pm = prior_means[cid_s[nb] * D + d];
            float pv = softplus_f(prior_vars[cid_s[nb] * D + d]);
            float diff = pm - m;
            term[nb] = v / pv + diff * diff / pv - 1.f + logf(pv) - logf(v);
        }
    }
    #pragma unroll
    for (int nb = 0; nb < NB; nb++) {
        float t = term[nb];
        #pragma unroll
        for (int o = 16; o; o >>= 1) t += __shfl_xor_sync(0xffffffffu, t, o);
        if (tid < D && (tid & 31) == 0) red_s[nb][tid >> 5] = t;
    }
    __syncthreads();
    if (tid < NB) {
        float s = red_s[tid][0] + red_s[tid][1] + red_s[tid][2] + red_s[tid][3];
        g_kl[b0 + tid] = 0.5f * s;
    }
}

// ---------------- kernel 2: dual-pipe vocab GEMM --------------------------------
// Every warp drives BOTH pipes: 96 cols via fp16 mma.sync (tensor) + 48 cols via
// fp32 FFMA (fma pipe), 2:1 ratio = measured pipe-capacity balance.
// Warp w owns rows [16w, 16w+16); thread (g,cg) owns rows r0=16w+g, r1=r0+8.
__global__ void __launch_bounds__(256, 2) vocab_kernel(
    const float* __restrict__ Wv, const float* __restrict__ bvoc)
{
    __shared__ unsigned            BH[2 * WSBUF];   // fp16 B tiles (13312 B)
    __shared__ __align__(16) float WF[2 * WFBUF];   // fp32 B tiles (12288 B)

    const int tid   = threadIdx.x;
    const int lane  = tid & 31;
    const int w     = tid >> 5;
    const int g     = lane >> 2;
    const int cg    = lane & 3;
    const int chunk = blockIdx.x;
    const int v0    = chunk * NW;
    const int b0    = blockIdx.y * M_CTA;

    const unsigned* zh0 = g_zh2 + (b0 + w * 16 + g) * (D / 2);
    const unsigned* zh1 = zh0 + 8 * (D / 2);
    const float*    zT  = g_zT + b0 + w * 16 + g;     // + k*B ; row r1 = +8

    float acc[12][4];                                  // HMMA accum
    #pragma unroll
    for (int t = 0; t < 12; t++)
        #pragma unroll
        for (int i = 0; i < 4; i++) acc[t][i] = 0.f;
    float fa0[12], fa1[12];                            // FFMA accum rows r0, r1
    #pragma unroll
    for (int j = 0; j < 12; j++) { fa0[j] = 0.f; fa1[j] = 0.f; }

    // prefetch registers
    float plo[6], phi[6], wf[6];

    #define LOAD_H(K0) do {                                                   \
        _Pragma("unroll")                                                     \
        for (int i = 0; i < 6; i++) {                                         \
            int idx = tid + 256 * i;                                          \
            int k2 = idx / HN, col = idx % HN;                                \
            int v = v0 + col;                                                 \
            bool okv = (v < V);                                               \
            const float* wp = Wv + (okv ? v : 0);                             \
            plo[i] = okv ? wp[((K0) + 2 * k2) * V] : 0.f;                     \
            phi[i] = okv ? wp[((K0) + 2 * k2 + 1) * V] : 0.f;                 \
        } } while (0)
    #define STORE_H(BUF) do {                                                 \
        _Pragma("unroll")                                                     \
        for (int i = 0; i < 6; i++) {                                         \
            int idx = tid + 256 * i;                                          \
            int k2 = idx / HN, col = idx % HN;                                \
            __half2 hv = __floats2half2_rn(plo[i], phi[i]);                   \
            (BUF)[k2 * WS2 + col] = *(unsigned*)&hv;                          \
        } } while (0)
    #define LOAD_F(K0) do {                                                   \
        _Pragma("unroll")                                                     \
        for (int i = 0; i < 6; i++) {                                         \
            int idx = tid + 256 * i;                                          \
            int kf = idx / FN, cf = idx % FN;                                 \
            int v = v0 + HN + cf;                                             \
            wf[i] = (v < V) ? Wv[((K0) + kf) * V + v] : 0.f;                  \
        } } while (0)
    #define STORE_F(BUF) do {                                                 \
        _Pragma("unroll")                                                     \
        for (int i = 0; i < 6; i++) {                                         \
            int idx = tid + 256 * i;                                          \
            int kf = idx / FN, cf = idx % FN;                                 \
            (BUF)[kf * WFS + cf] = wf[i];                                     \
        } } while (0)

    LOAD_H(0);
    LOAD_F(0);
    #pragma unroll
    for (int it = 0; it < 4; it++) {
        unsigned* bufH = BH + (it & 1) * WSBUF;
        float*    bufF = WF + (it & 1) * WFBUF;
        STORE_H(bufH);
        STORE_F(bufF);
        __syncthreads();
        if (it < 3) { LOAD_H((it + 1) * KT); LOAD_F((it + 1) * KT); }

        const int k0 = it * KT;
        #pragma unroll
        for (int half = 0; half < 2; half++) {
            const int ks = half * 16;
            // ---- tensor pipe: 12 m16n8k16 ----
            const int kh = (k0 + ks) >> 1;
            unsigned a0 = zh0[kh + cg];
            unsigned a1 = zh1[kh + cg];
            unsigned a2 = zh0[kh + cg + 4];
            unsigned a3 = zh1[kh + cg + 4];
            const unsigned* wsb0 = bufH + ((ks >> 1) + cg) * WS2 + g;
            const unsigned* wsb1 = wsb0 + 4 * WS2;
            #pragma unroll
            for (int t = 0; t < 12; t++)
                mma_f16(acc[t], a0, a1, a2, a3, wsb0[t * 8], wsb1[t * 8]);
            // ---- fma pipe: 12 cols x 2 rows x 16 k ----
            #pragma unroll
            for (int kk = 0; kk < 16; kk++) {
                float z0 = __ldg(&zT[(k0 + ks + kk) * B]);
                float z1 = __ldg(&zT[(k0 + ks + kk) * B + 8]);
                const float* wr = bufF + (ks + kk) * WFS + cg * 12;
                float4 w0 = *(const float4*)&wr[0];
                float4 w1 = *(const float4*)&wr[4];
                float4 w2 = *(const float4*)&wr[8];
                fa0[0] = fmaf(z0, w0.x, fa0[0]);  fa1[0]  = fmaf(z1, w0.x, fa1[0]);
                fa0[1] = fmaf(z0, w0.y, fa0[1]);  fa1[1]  = fmaf(z1, w0.y, fa1[1]);
                fa0[2] = fmaf(z0, w0.z, fa0[2]);  fa1[2]  = fmaf(z1, w0.z, fa1[2]);
                fa0[3] = fmaf(z0, w0.w, fa0[3]);  fa1[3]  = fmaf(z1, w0.w, fa1[3]);
                fa0[4] = fmaf(z0, w1.x, fa0[4]);  fa1[4]  = fmaf(z1, w1.x, fa1[4]);
                fa0[5] = fmaf(z0, w1.y, fa0[5]);  fa1[5]  = fmaf(z1, w1.y, fa1[5]);
                fa0[6] = fmaf(z0, w1.z, fa0[6]);  fa1[6]  = fmaf(z1, w1.z, fa1[6]);
                fa0[7] = fmaf(z0, w1.w, fa0[7]);  fa1[7]  = fmaf(z1, w1.w, fa1[7]);
                fa0[8] = fmaf(z0, w2.x, fa0[8]);  fa1[8]  = fmaf(z1, w2.x, fa1[8]);
                fa0[9] = fmaf(z0, w2.y, fa0[9]);  fa1[9]  = fmaf(z1, w2.y, fa1[9]);
                fa0[10] = fmaf(z0, w2.z, fa0[10]); fa1[10] = fmaf(z1, w2.z, fa1[10]);
                fa0[11] = fmaf(z0, w2.w, fa0[11]); fa1[11] = fmaf(z1, w2.w, fa1[11]);
            }
        }
        __syncthreads();
    }
    #undef LOAD_H
    #undef STORE_H
    #undef LOAD_F
    #undef STORE_F

    // ---------------- epilogue: bias + mask + per-row max/sumexp over NW cols ----
    float m0 = -INFINITY, m1 = -INFINITY;
    #pragma unroll
    for (int t = 0; t < 12; t++) {
        int n = t * 8 + 2 * cg;
        bool ok0 = (v0 + n) < V;
        bool ok1 = (v0 + n + 1) < V;
        float bv0 = ok0 ? bvoc[v0 + n] : 0.f;
        float bv1 = ok1 ? bvoc[v0 + n + 1] : 0.f;
        acc[t][0] = ok0 ? acc[t][0] + bv0 : -INFINITY;
        acc[t][1] = ok1 ? acc[t][1] + bv1 : -INFINITY;
        acc[t][2] = ok0 ? acc[t][2] + bv0 : -INFINITY;
        acc[t][3] = ok1 ? acc[t][3] + bv1 : -INFINITY;
        m0 = fmaxf(m0, fmaxf(acc[t][0], acc[t][1]));
        m1 = fmaxf(m1, fmaxf(acc[t][2], acc[t][3]));
    }
    #pragma unroll
    for (int j = 0; j < 12; j++) {
        int v = v0 + HN + cg * 12 + j;
        bool ok = (v < V);
        float bv = ok ? bvoc[v] : 0.f;
        fa0[j] = ok ? fa0[j] + bv : -INFINITY;
        fa1[j] = ok ? fa1[j] + bv : -INFINITY;
        m0 = fmaxf(m0, fa0[j]);
        m1 = fmaxf(m1, fa1[j]);
    }
    #pragma unroll
    for (int o = 1; o <= 2; o <<= 1) {
        m0 = fmaxf(m0, __shfl_xor_sync(0xffffffffu, m0, o));
        m1 = fmaxf(m1, __shfl_xor_sync(0xffffffffu, m1, o));
    }
    m0 = fmaxf(m0, -1e30f);   // avoid -inf - -inf = NaN on all-masked threads
    m1 = fmaxf(m1, -1e30f);
    float s0 = 0.f, s1 = 0.f;
    #pragma unroll
    for (int t = 0; t < 12; t++) {
        s0 += __expf(acc[t][0] - m0) + __expf(acc[t][1] - m0);
        s1 += __expf(acc[t][2] - m1) + __expf(acc[t][3] - m1);
    }
    #pragma unroll
    for (int j = 0; j < 12; j++) {
        s0 += __expf(fa0[j] - m0);
        s1 += __expf(fa1[j] - m1);
    }
    #pragma unroll
    for (int o = 1; o <= 2; o <<= 1) {
        s0 += __shfl_xor_sync(0xffffffffu, s0, o);
        s1 += __shfl_xor_sync(0xffffffffu, s1, o);
    }
    if (cg == 0) {
        int r0 = b0 + w * 16 + g;
        g_pmax[r0 * NCHUNK + chunk] = m0;
        g_psum[r0 * NCHUNK + chunk] = s0;
        g_pmax[(r0 + 8) * NCHUNK + chunk] = m1;
        g_psum[(r0 + 8) * NCHUNK + chunk] = s1;
    }
}

// ---------------- kernel 3: per-row logsumexp combine + context gather ----------------
__global__ void __launch_bounds__(128) finalize_rows(
    const float* __restrict__ Wv, const float* __restrict__ bvoc,
    const int* __restrict__ context_ids)
{
    const int warp = threadIdx.x >> 5;
    const int lane = threadIdx.x & 31;
    const int b = blockIdx.x * 4 + warp;

    float m = -INFINITY, s = 0.f;
    for (int ch = lane; ch < NCHUNK; ch += 32) {
        float m2 = g_pmax[b * NCHUNK + ch];
        float s2 = g_psum[b * NCHUNK + ch];
        if (m2 > m) { s = s * __expf(m - m2) + s2; m = m2; }
        else        { s += s2 * __expf(m2 - m); }
    }
    #pragma unroll
    for (int o = 16; o; o >>= 1) {
        float m2 = __shfl_xor_sync(0xffffffffu, m, o);
        float s2 = __shfl_xor_sync(0xffffffffu, s, o);
        if (m2 > m) { s = s * __expf(m - m2) + s2; m = m2; }
        else        { s += s2 * __expf(m2 - m); }
    }
    float lse = m + logf(s);

    float zr[4];
    #pragma unroll
    for (int t = 0; t < 4; t++) zr[t] = g_z[b * D + lane + 32 * t];

    float rec = 0.f;
    #pragma unroll
    for (int c = 0; c < C; c++) {
        int v = context_ids[b * C + c];
        float p = 0.f;
        #pragma unroll
        for (int t = 0; t < 4; t++)
            p = fmaf(zr[t], Wv[(lane + 32 * t) * V + v], p);
        #pragma unroll
        for (int o = 16; o; o >>= 1) p += __shfl_xor_sync(0xffffffffu, p, o);
        rec += p + bvoc[v] - lse;
    }
    if (lane == 0) g_rowval[b] = rec - g_kl[b];
}

// ---------------- kernel 4: deterministic mean over B ----------------
__global__ void __launch_bounds__(1024) reduce_mean(float* __restrict__ out)
{
    __shared__ float red_s[32];
    const int tid = threadIdx.x;
    float v = g_rowval[tid];
    #pragma unroll
    for (int o = 16; o; o >>= 1) v += __shfl_xor_sync(0xffffffffu, v, o);
    if ((tid & 31) == 0) red_s[tid >> 5] = v;
    __syncthreads();
    if (tid < 32) {
        float sv = red_s[tid];
        #pragma unroll
        for (int o = 16; o; o >>= 1) sv += __shfl_xor_sync(0xffffffffu, sv, o);
        if (tid == 0) out[0] = sv * (1.0f / (float)B);
    }
}

// ---------------- launch ----------------
extern "C" void kernel_launch(void* const* d_in, const int* in_sizes, int n_in,
                              void* d_out, int out_size)
{
    const int*   center_id   = (const int*)d_in[0];
    const int*   context_ids = (const int*)d_in[1];
    const float* epsilon     = (const float*)d_in[2];
    const float* emb         = (const float*)d_in[3];
    const float* prior_means = (const float*)d_in[4];
    const float* prior_vars  = (const float*)d_in[5];
    const float* W_enc       = (const float*)d_in[6];
    const float* b_enc       = (const float*)d_in[7];
    const float* W_mean      = (const float*)d_in[8];
    const float* b_mean      = (const float*)d_in[9];
    const float* W_var       = (const float*)d_in[10];
    const float* b_var       = (const float*)d_in[11];
    const float* W_vocab     = (const float*)d_in[12];
    const float* b_vocab     = (const float*)d_in[13];
    float* out = (float*)d_out;

    encoder_kernel<<<B / NB, 256>>>(center_id, context_ids, epsilon, emb,
                                    prior_means, prior_vars,
                                    W_enc, b_enc, W_mean, b_mean, W_var, b_var);

    dim3 grid2(NCHUNK, B / M_CTA);
    vocab_kernel<<<grid2, 256>>>(W_vocab, b_vocab);

    finalize_rows<<<B / 4, 128>>>(W_vocab, b_vocab, context_ids);

    reduce_mean<<<1, 1024>>>(out);
}

// round 8
// speedup vs baseline: 2.6285x; 1.9415x over previous
#include <cuda_runtime.h>
#include <cuda_fp16.h>
#include <cuda_bf16.h>
#include <math.h>
#include <stdint.h>

#define V 50257
#define D 128
#define B 1024
#define C 10
#define TWO_D 256
#define NB 4                 // batch rows per encoder CTA

// vocab GEMM tiling (fp16 mma.sync m16n8k16)
#define M_CTA 128
#define N_CTA 128
#define KT 32                              // k per smem stage (16 half2 rows)
#define WS_STRIDE 136                      // half2 units; conflict-free fragment loads
#define WS_BUF (16 * WS_STRIDE)            // 2176 words per stage
#define NCHUNK ((V + N_CTA - 1) / N_CTA)   // 393
#define FIN_BLOCKS (B / 4)                 // finalize: 4 rows per block

// ---------------- scratch ----------------
__device__ float              g_z[B * D];
__device__ unsigned           g_zh2[B * D / 2];   // packed half2 z
__device__ float              g_kl[B];
__device__ float              g_pmax[B * NCHUNK];
__device__ float              g_psum[B * NCHUNK];
__device__ long long          g_acc;              // fixed-point sum of (rec-kl)
__device__ unsigned int       g_done;             // finalize block counter

__device__ __forceinline__ float softplus_f(float x) {
    return fmaxf(x, 0.f) + log1pf(expf(-fabsf(x)));
}

__device__ __forceinline__ void mma_f16(float c[4],
                                        unsigned a0, unsigned a1, unsigned a2, unsigned a3,
                                        unsigned b0, unsigned b1) {
    asm volatile(
        "mma.sync.aligned.m16n8k16.row.col.f32.f16.f16.f32 "
        "{%0,%1,%2,%3}, {%4,%5,%6,%7}, {%8,%9}, {%0,%1,%2,%3};"
        : "+f"(c[0]), "+f"(c[1]), "+f"(c[2]), "+f"(c[3])
        : "r"(a0), "r"(a1), "r"(a2), "r"(a3), "r"(b0), "r"(b1));
}

// ---------------- kernel 1: encoder (NB=4 rows/CTA) + heads + KL + z ----------------
__global__ void __launch_bounds__(256) encoder_kernel(
    const int* __restrict__ center_id, const int* __restrict__ context_ids,
    const float* __restrict__ epsilon, const float* __restrict__ emb,
    const float* __restrict__ prior_means, const float* __restrict__ prior_vars,
    const float* __restrict__ W_enc, const float* __restrict__ b_enc,
    const float* __restrict__ W_mean, const float* __restrict__ b_mean,
    const float* __restrict__ W_var, const float* __restrict__ b_var)
{
    __shared__ float ce_s[NB][D];
    __shared__ float cx_s[NB][C][D];
    __shared__ float h_s[NB][TWO_D];
    __shared__ float mean_s[NB][D];
    __shared__ float var_s[NB][D];
    __shared__ int   ctx_s[NB][C];
    __shared__ int   cid_s[NB];
    __shared__ float red_s[NB][4];

    const int b0  = blockIdx.x * NB;
    const int tid = threadIdx.x;

    // reset the global accumulator/counter for this invocation (stream-ordered
    // before the finalize kernel; done by every replay -> deterministic)
    if (blockIdx.x == 0 && tid == 0) { g_acc = 0ll; g_done = 0u; }

    if (tid < NB) cid_s[tid] = center_id[b0 + tid];
    if (tid < NB * C) ctx_s[tid / C][tid % C] = context_ids[b0 * C + tid];
    __syncthreads();
    for (int e = tid; e < NB * D; e += 256) {
        int nb = e >> 7, d = e & 127;
        ce_s[nb][d] = emb[cid_s[nb] * D + d];
    }
    for (int e = tid; e < NB * C * D; e += 256) {
        int nb = e / (C * D), r = e % (C * D);
        int c = r >> 7, d = r & 127;
        cx_s[nb][c][d] = emb[ctx_s[nb][c] * D + d];
    }
    __syncthreads();

    const int j = tid;
    float cepart[NB];
    #pragma unroll
    for (int nb = 0; nb < NB; nb++) cepart[nb] = 0.f;
    #pragma unroll 2
    for (int k = 0; k < D; k++) {
        float w1 = W_enc[k * TWO_D + j];
        #pragma unroll
        for (int nb = 0; nb < NB; nb++)
            cepart[nb] = fmaf(ce_s[nb][k], w1, cepart[nb]);
    }

    float acc[NB][C];
    #pragma unroll
    for (int nb = 0; nb < NB; nb++)
        #pragma unroll
        for (int c = 0; c < C; c++) acc[nb][c] = 0.f;
    for (int k = 0; k < D; k++) {
        float w2 = W_enc[(D + k) * TWO_D + j];
        #pragma unroll
        for (int nb = 0; nb < NB; nb++)
            #pragma unroll
            for (int c = 0; c < C; c++)
                acc[nb][c] = fmaf(cx_s[nb][c][k], w2, acc[nb][c]);
    }
    float be = b_enc[j];
    #pragma unroll
    for (int nb = 0; nb < NB; nb++) {
        float base = cepart[nb] + be;
        float hj = 0.f;
        #pragma unroll
        for (int c = 0; c < C; c++) hj += fmaxf(acc[nb][c] + base, 0.f);
        h_s[nb][j] = hj;
    }
    __syncthreads();

    if (tid < D) {
        int d = tid;
        float m[NB];
        #pragma unroll
        for (int nb = 0; nb < NB; nb++) m[nb] = b_mean[d];
        #pragma unroll 2
        for (int k = 0; k < TWO_D; k++) {
            float wm = W_mean[k * D + d];
            #pragma unroll
            for (int nb = 0; nb < NB; nb++)
                m[nb] = fmaf(h_s[nb][k], wm, m[nb]);
        }
        #pragma unroll
        for (int nb = 0; nb < NB; nb++) mean_s[nb][d] = m[nb];
    } else {
        int d = tid - D;
        float vr[NB];
        #pragma unroll
        for (int nb = 0; nb < NB; nb++) vr[nb] = b_var[d];
        #pragma unroll 2
        for (int k = 0; k < TWO_D; k++) {
            float wv = W_var[k * D + d];
            #pragma unroll
            for (int nb = 0; nb < NB; nb++)
                vr[nb] = fmaf(h_s[nb][k], wv, vr[nb]);
        }
        #pragma unroll
        for (int nb = 0; nb < NB; nb++) var_s[nb][d] = softplus_f(vr[nb]);
    }
    __syncthreads();

    float term[NB];
    #pragma unroll
    for (int nb = 0; nb < NB; nb++) term[nb] = 0.f;
    if (tid < D) {
        int d = tid;
        float eps = epsilon[d];
        #pragma unroll
        for (int nb = 0; nb < NB; nb++) {
            int b = b0 + nb;
            float m = mean_s[nb][d];
            float v = var_s[nb][d];
            float z = m + expf(0.5f * v) * eps;
            g_z[b * D + d] = z;
            float zn = __shfl_down_sync(0xffffffffu, z, 1);
            if (!(d & 1)) {
                __half2 hz = __floats2half2_rn(z, zn);
                g_zh2[(b * D + d) >> 1] = *(unsigned*)&hz;
            }
            float pm = prior_means[cid_s[nb] * D + d];
            float pv = softplus_f(prior_vars[cid_s[nb] * D + d]);
            float diff = pm - m;
            term[nb] = v / pv + diff * diff / pv - 1.f + logf(pv) - logf(v);
        }
    }
    #pragma unroll
    for (int nb = 0; nb < NB; nb++) {
        float t = term[nb];
        #pragma unroll
        for (int o = 16; o; o >>= 1) t += __shfl_xor_sync(0xffffffffu, t, o);
        if (tid < D && (tid & 31) == 0) red_s[nb][tid >> 5] = t;
    }
    __syncthreads();
    if (tid < NB) {
        float s = red_s[tid][0] + red_s[tid][1] + red_s[tid][2] + red_s[tid][3];
        g_kl[b0 + tid] = 0.5f * s;
    }
}

// ---------------- kernel 2: fp16 mma.sync vocab GEMM + fused softmax partials ----
// CTA: 128 rows x 128 vocab cols; 8 warps; warp w owns rows [16w,16w+16).
// A (z half2) from global (L1/L2-hot); B (W_vocab) half2-packed in smem,
// double-buffered, register-prefetched. Stride 136 -> conflict-free.
__global__ void __launch_bounds__(256, 2) vocab_kernel(
    const float* __restrict__ Wv, const float* __restrict__ bvoc)
{
    __shared__ unsigned Ws[2 * WS_BUF];     // 17408 B

    const int tid  = threadIdx.x;
    const int lane = tid & 31;
    const int w    = tid >> 5;
    const int g    = lane >> 2;
    const int cg   = lane & 3;
    const int v0   = blockIdx.x * N_CTA;
    const int b0   = blockIdx.y * M_CTA;

    const unsigned* zh0 = g_zh2 + (b0 + w * 16 + g) * (D / 2);
    const unsigned* zh1 = zh0 + 8 * (D / 2);

    const int n_f  = tid & 127;
    const int k2b  = tid >> 7;
    const int vf   = v0 + n_f;
    const bool okf = (vf < V);
    const float* wp = Wv + (okf ? vf : 0);

    float acc[16][4];
    #pragma unroll
    for (int t = 0; t < 16; t++)
        #pragma unroll
        for (int i = 0; i < 4; i++) acc[t][i] = 0.f;

    float plo[8], phi[8];
    #define LOADREGS(K0) do {                                                 \
        _Pragma("unroll")                                                     \
        for (int i = 0; i < 8; i++) {                                         \
            int kk = (K0) + 2 * (k2b + 2 * i);                                \
            plo[i] = okf ? wp[kk * V] : 0.f;                                  \
            phi[i] = okf ? wp[(kk + 1) * V] : 0.f;                            \
        } } while (0)
    #define STOREREGS(BUF) do {                                               \
        _Pragma("unroll")                                                     \
        for (int i = 0; i < 8; i++) {                                         \
            __half2 hv = __floats2half2_rn(plo[i], phi[i]);                   \
            (BUF)[(k2b + 2 * i) * WS_STRIDE + n_f] = *(unsigned*)&hv;         \
        } } while (0)

    LOADREGS(0);
    #pragma unroll
    for (int it = 0; it < 4; it++) {
        unsigned* buf = Ws + (it & 1) * WS_BUF;
        STOREREGS(buf);
        __syncthreads();
        if (it < 3) LOADREGS((it + 1) * KT);

        const int k0 = it * KT;
        #pragma unroll
        for (int ks = 0; ks < KT; ks += 16) {
            const int kh = (k0 + ks) >> 1;
            unsigned a0 = zh0[kh + cg];
            unsigned a1 = zh1[kh + cg];
            unsigned a2 = zh0[kh + cg + 4];
            unsigned a3 = zh1[kh + cg + 4];
            const unsigned* wsb0 = buf + ((ks >> 1) + cg) * WS_STRIDE + g;
            const unsigned* wsb1 = wsb0 + 4 * WS_STRIDE;
            #pragma unroll
            for (int t = 0; t < 16; t++)
                mma_f16(acc[t], a0, a1, a2, a3, wsb0[t * 8], wsb1[t * 8]);
        }
    }
    #undef LOADREGS
    #undef STOREREGS

    // epilogue: bias + mask + per-row max/sumexp over this 128-col chunk
    const int chunk = blockIdx.x;
    float m0 = -INFINITY, m1 = -INFINITY;
    #pragma unroll
    for (int t = 0; t < 16; t++) {
        int n = t * 8 + 2 * cg;
        bool ok0 = (v0 + n) < V;
        bool ok1 = (v0 + n + 1) < V;
        float bv0 = ok0 ? bvoc[v0 + n] : 0.f;
        float bv1 = ok1 ? bvoc[v0 + n + 1] : 0.f;
        acc[t][0] = ok0 ? acc[t][0] + bv0 : -INFINITY;
        acc[t][1] = ok1 ? acc[t][1] + bv1 : -INFINITY;
        acc[t][2] = ok0 ? acc[t][2] + bv0 : -INFINITY;
        acc[t][3] = ok1 ? acc[t][3] + bv1 : -INFINITY;
        m0 = fmaxf(m0, fmaxf(acc[t][0], acc[t][1]));
        m1 = fmaxf(m1, fmaxf(acc[t][2], acc[t][3]));
    }
    #pragma unroll
    for (int o = 1; o <= 2; o <<= 1) {
        m0 = fmaxf(m0, __shfl_xor_sync(0xffffffffu, m0, o));
        m1 = fmaxf(m1, __shfl_xor_sync(0xffffffffu, m1, o));
    }
    float s0 = 0.f, s1 = 0.f;
    #pragma unroll
    for (int t = 0; t < 16; t++) {
        s0 += __expf(acc[t][0] - m0) + __expf(acc[t][1] - m0);
        s1 += __expf(acc[t][2] - m1) + __expf(acc[t][3] - m1);
    }
    #pragma unroll
    for (int o = 1; o <= 2; o <<= 1) {
        s0 += __shfl_xor_sync(0xffffffffu, s0, o);
        s1 += __shfl_xor_sync(0xffffffffu, s1, o);
    }
    if (cg == 0) {
        int r0 = b0 + w * 16 + g;
        g_pmax[r0 * NCHUNK + chunk] = m0;
        g_psum[r0 * NCHUNK + chunk] = s0;
        g_pmax[(r0 + 8) * NCHUNK + chunk] = m1;
        g_psum[(r0 + 8) * NCHUNK + chunk] = s1;
    }
}

// ---------------- kernel 3: logsumexp combine + context gather + FUSED mean ----
// Per-row value accumulated into a fixed-point int64 (order-independent ->
// deterministic); the last block to finish converts and writes the mean.
__global__ void __launch_bounds__(128) finalize_rows(
    const float* __restrict__ Wv, const float* __restrict__ bvoc,
    const int* __restrict__ context_ids, float* __restrict__ out)
{
    __shared__ long long blk_s[4];

    const int warp = threadIdx.x >> 5;
    const int lane = threadIdx.x & 31;
    const int b = blockIdx.x * 4 + warp;

    float m = -INFINITY, s = 0.f;
    for (int ch = lane; ch < NCHUNK; ch += 32) {
        float m2 = g_pmax[b * NCHUNK + ch];
        float s2 = g_psum[b * NCHUNK + ch];
        if (m2 > m) { s = s * __expf(m - m2) + s2; m = m2; }
        else        { s += s2 * __expf(m2 - m); }
    }
    #pragma unroll
    for (int o = 16; o; o >>= 1) {
        float m2 = __shfl_xor_sync(0xffffffffu, m, o);
        float s2 = __shfl_xor_sync(0xffffffffu, s, o);
        if (m2 > m) { s = s * __expf(m - m2) + s2; m = m2; }
        else        { s += s2 * __expf(m2 - m); }
    }
    float lse = m + logf(s);

    float zr[4];
    #pragma unroll
    for (int t = 0; t < 4; t++) zr[t] = g_z[b * D + lane + 32 * t];

    float rec = 0.f;
    #pragma unroll
    for (int c = 0; c < C; c++) {
        int v = context_ids[b * C + c];
        float p = 0.f;
        #pragma unroll
        for (int t = 0; t < 4; t++)
            p = fmaf(zr[t], Wv[(lane + 32 * t) * V + v], p);
        #pragma unroll
        for (int o = 16; o; o >>= 1) p += __shfl_xor_sync(0xffffffffu, p, o);
        rec += p + bvoc[v] - lse;
    }

    // fixed-point per-block sum (4 rows), then one atomicAdd per block
    if (lane == 0) {
        float val = rec - g_kl[b];
        blk_s[warp] = __double2ll_rn((double)val * 4294967296.0);
    }
    __syncthreads();
    if (threadIdx.x == 0) {
        long long bs = blk_s[0] + blk_s[1] + blk_s[2] + blk_s[3];
        atomicAdd((unsigned long long*)&g_acc, (unsigned long long)bs);
        __threadfence();
        unsigned int done = atomicAdd(&g_done, 1u);
        if (done == FIN_BLOCKS - 1) {
            long long tot = *(volatile long long*)&g_acc;
            out[0] = (float)((double)tot * (1.0 / 4294967296.0) * (1.0 / (double)B));
        }
    }
}

// ---------------- launch ----------------
extern "C" void kernel_launch(void* const* d_in, const int* in_sizes, int n_in,
                              void* d_out, int out_size)
{
    const int*   center_id   = (const int*)d_in[0];
    const int*   context_ids = (const int*)d_in[1];
    const float* epsilon     = (const float*)d_in[2];
    const float* emb         = (const float*)d_in[3];
    const float* prior_means = (const float*)d_in[4];
    const float* prior_vars  = (const float*)d_in[5];
    const float* W_enc       = (const float*)d_in[6];
    const float* b_enc       = (const float*)d_in[7];
    const float* W_mean      = (const float*)d_in[8];
    const float* b_mean      = (const float*)d_in[9];
    const float* W_var       = (const float*)d_in[10];
    const float* b_var       = (const float*)d_in[11];
    const float* W_vocab     = (const float*)d_in[12];
    const float* b_vocab     = (const float*)d_in[13];
    float* out = (float*)d_out;

    encoder_kernel<<<B / NB, 256>>>(center_id, context_ids, epsilon, emb,
                                    prior_means, prior_vars,
                                    W_enc, b_enc, W_mean, b_mean, W_var, b_var);

    dim3 grid2(NCHUNK, B / M_CTA);
    vocab_kernel<<<grid2, 256>>>(W_vocab, b_vocab);

    finalize_rows<<<FIN_BLOCKS, 128>>>(W_vocab, b_vocab, context_ids, out);
}

// round 12
// speedup vs baseline: 2.9278x; 1.1139x over previous
#include <cuda_runtime.h>
#include <cuda_fp16.h>
#include <cuda_bf16.h>
#include <math.h>
#include <stdint.h>

#define V 50257
#define D 128
#define B 1024
#define C 10
#define TWO_D 256
#define NB 4                 // batch rows per encoder CTA
#define NROW (NB * C)        // 40 cx rows per CTA

// vocab GEMM tiling (fp16 mma.sync m16n8k16)
#define M_CTA 128
#define N_CTA 128
#define KT 32
#define WS_STRIDE 136
#define WS_BUF (16 * WS_STRIDE)
#define NCHUNK ((V + N_CTA - 1) / N_CTA)   // 393
#define FIN_BLOCKS (B / 4)

// encoder smem layout (floats)
#define EO_A      0            // A_s   [40*128] = 5120
#define EO_CE     5120         // ce_s  [4*128]  = 512
#define EO_CP     5632         // cepart[4*256]  = 1024
#define EO_B      6656         // B_s   [16*256] = 4096 (main loop)  -> ends 10752
#define EO_HW     6656         // hw_s  [8*256]  = 2048 (post, aliases B)
#define EO_H      8704         // h_s   [4*256]  = 1024 (post, aliases B)
#define EO_MEAN   0            // mean_s[4*128]  = 512  (post, aliases A)
#define EO_VAR    512          // var_s [4*128]  = 512  (post, aliases A)
#define EO_TOTAL  10752        // FIX: must cover EO_B + 4096

// ---------------- scratch ----------------
__device__ float              g_z[B * D];
__device__ unsigned           g_zh2[B * D / 2];
__device__ float              g_kl[B];
__device__ float              g_pmax[B * NCHUNK];
__device__ float              g_psum[B * NCHUNK];
__device__ long long          g_acc;
__device__ unsigned int       g_done;

__device__ __forceinline__ float softplus_f(float x) {
    return fmaxf(x, 0.f) + log1pf(expf(-fabsf(x)));
}

__device__ __forceinline__ void mma_f16(float c[4],
                                        unsigned a0, unsigned a1, unsigned a2, unsigned a3,
                                        unsigned b0, unsigned b1) {
    asm volatile(
        "mma.sync.aligned.m16n8k16.row.col.f32.f16.f16.f32 "
        "{%0,%1,%2,%3}, {%4,%5,%6,%7}, {%8,%9}, {%0,%1,%2,%3};"
        : "+f"(c[0]), "+f"(c[1]), "+f"(c[2]), "+f"(c[3])
        : "r"(a0), "r"(a1), "r"(a2), "r"(a3), "r"(b0), "r"(b1));
}

// ---------------- kernel 1: register-tiled encoder + heads + KL + z ----------------
// cx GEMM [40,128]@[128,256]: 8 warps x 5 rows; thread = 5 rows x (4+4) cols.
__global__ void __launch_bounds__(256) encoder_kernel(
    const int* __restrict__ center_id, const int* __restrict__ context_ids,
    const float* __restrict__ epsilon, const float* __restrict__ emb,
    const float* __restrict__ prior_means, const float* __restrict__ prior_vars,
    const float* __restrict__ W_enc, const float* __restrict__ b_enc,
    const float* __restrict__ W_mean, const float* __restrict__ b_mean,
    const float* __restrict__ W_var, const float* __restrict__ b_var)
{
    __shared__ float S[EO_TOTAL];
    __shared__ int   ctx_s[NROW];
    __shared__ int   cid_s[NB];
    __shared__ float red_s[NB][4];

    const int b0   = blockIdx.x * NB;
    const int tid  = threadIdx.x;
    const int lane = tid & 31;
    const int w    = tid >> 5;
    const int l4   = lane * 4;

    if (blockIdx.x == 0 && tid == 0) { g_acc = 0ll; g_done = 0u; }

    if (tid < NB)   cid_s[tid] = center_id[b0 + tid];
    if (tid < NROW) ctx_s[tid] = context_ids[b0 * C + tid];
    __syncthreads();

    // gather ce (4x128) and A = cx (40x128), float4-coalesced
    if (tid < NB * 32) {
        int row = tid >> 5, l = tid & 31;
        *(float4*)&S[EO_CE + row * D + l * 4] =
            *(const float4*)&emb[cid_s[row] * D + l * 4];
    }
    for (int e = tid; e < NROW * 32; e += 256) {
        int row = e >> 5, l = e & 31;
        *(float4*)&S[EO_A + row * D + l * 4] =
            *(const float4*)&emb[ctx_s[row] * D + l * 4];
    }
    __syncthreads();

    // cepart[nb][j] = ce_nb . W1[:,j]   (j = tid)
    {
        const int j = tid;
        float cp[NB] = {0.f, 0.f, 0.f, 0.f};
        #pragma unroll 4
        for (int k = 0; k < D; k++) {
            float w1 = W_enc[k * TWO_D + j];
            #pragma unroll
            for (int nb = 0; nb < NB; nb++)
                cp[nb] = fmaf(S[EO_CE + nb * D + k], w1, cp[nb]);
        }
        #pragma unroll
        for (int nb = 0; nb < NB; nb++) S[EO_CP + nb * TWO_D + j] = cp[nb];
    }

    // ---- main cx GEMM, W2 staged in 16-k tiles, register prefetch ----
    float acc[5][8];
    #pragma unroll
    for (int i = 0; i < 5; i++)
        #pragma unroll
        for (int j = 0; j < 8; j++) acc[i][j] = 0.f;

    const float* W2 = W_enc + D * TWO_D;
    float4 pf[4];
    #pragma unroll
    for (int i = 0; i < 4; i++)
        pf[i] = *(const float4*)(W2 + tid * 4 + i * 1024);

    const int arow = w * 5 * D;
    #pragma unroll 1
    for (int kt = 0; kt < 8; kt++) {
        __syncthreads();                       // B_s readers from prev iter done
        #pragma unroll
        for (int i = 0; i < 4; i++)
            *(float4*)&S[EO_B + tid * 4 + i * 1024] = pf[i];
        __syncthreads();
        if (kt < 7) {
            #pragma unroll
            for (int i = 0; i < 4; i++)
                pf[i] = *(const float4*)(W2 + (kt + 1) * 4096 + tid * 4 + i * 1024);
        }
        const int kb = kt * 16;
        #pragma unroll
        for (int kk = 0; kk < 16; kk++) {
            float4 bv0 = *(float4*)&S[EO_B + kk * TWO_D + l4];
            float4 bv1 = *(float4*)&S[EO_B + kk * TWO_D + 128 + l4];
            #pragma unroll
            for (int i = 0; i < 5; i++) {
                float a = S[EO_A + arow + i * D + kb + kk];
                acc[i][0] = fmaf(a, bv0.x, acc[i][0]);
                acc[i][1] = fmaf(a, bv0.y, acc[i][1]);
                acc[i][2] = fmaf(a, bv0.z, acc[i][2]);
                acc[i][3] = fmaf(a, bv0.w, acc[i][3]);
                acc[i][4] = fmaf(a, bv1.x, acc[i][4]);
                acc[i][5] = fmaf(a, bv1.y, acc[i][5]);
                acc[i][6] = fmaf(a, bv1.z, acc[i][6]);
                acc[i][7] = fmaf(a, bv1.w, acc[i][7]);
            }
        }
    }
    __syncthreads();    // all B_s reads done before hw_s (aliased) writes

    // ---- epilogue: relu(acc + cepart + b_enc), sum over 5 rows -> warp partial ----
    {
        const int nb = w >> 1;
        float4 cp0 = *(float4*)&S[EO_CP + nb * TWO_D + l4];
        float4 cp1 = *(float4*)&S[EO_CP + nb * TWO_D + 128 + l4];
        float4 be0 = *(const float4*)&b_enc[l4];
        float4 be1 = *(const float4*)&b_enc[128 + l4];
        float hp[8];
        #pragma unroll
        for (int j = 0; j < 8; j++) hp[j] = 0.f;
        #pragma unroll
        for (int i = 0; i < 5; i++) {
            hp[0] += fmaxf(acc[i][0] + cp0.x + be0.x, 0.f);
            hp[1] += fmaxf(acc[i][1] + cp0.y + be0.y, 0.f);
            hp[2] += fmaxf(acc[i][2] + cp0.z + be0.z, 0.f);
            hp[3] += fmaxf(acc[i][3] + cp0.w + be0.w, 0.f);
            hp[4] += fmaxf(acc[i][4] + cp1.x + be1.x, 0.f);
            hp[5] += fmaxf(acc[i][5] + cp1.y + be1.y, 0.f);
            hp[6] += fmaxf(acc[i][6] + cp1.z + be1.z, 0.f);
            hp[7] += fmaxf(acc[i][7] + cp1.w + be1.w, 0.f);
        }
        *(float4*)&S[EO_HW + w * TWO_D + l4]       = make_float4(hp[0], hp[1], hp[2], hp[3]);
        *(float4*)&S[EO_HW + w * TWO_D + 128 + l4] = make_float4(hp[4], hp[5], hp[6], hp[7]);
    }
    __syncthreads();
    // combine warp pairs -> h[nb][j]
    for (int e = tid; e < NB * TWO_D; e += 256) {
        int nb = e >> 8, j = e & 255;
        S[EO_H + e] = S[EO_HW + (2 * nb) * TWO_D + j] + S[EO_HW + (2 * nb + 1) * TWO_D + j];
    }
    __syncthreads();

    // ---- heads: mean (threads 0..127), softplus(var) (threads 128..255) ----
    if (tid < D) {
        int d = tid;
        float m[NB];
        #pragma unroll
        for (int nb = 0; nb < NB; nb++) m[nb] = b_mean[d];
        #pragma unroll 2
        for (int k = 0; k < TWO_D; k++) {
            float wm = W_mean[k * D + d];
            #pragma unroll
            for (int nb = 0; nb < NB; nb++)
                m[nb] = fmaf(S[EO_H + nb * TWO_D + k], wm, m[nb]);
        }
        #pragma unroll
        for (int nb = 0; nb < NB; nb++) S[EO_MEAN + nb * D + d] = m[nb];
    } else {
        int d = tid - D;
        float vr[NB];
        #pragma unroll
        for (int nb = 0; nb < NB; nb++) vr[nb] = b_var[d];
        #pragma unroll 2
        for (int k = 0; k < TWO_D; k++) {
            float wv = W_var[k * D + d];
            #pragma unroll
            for (int nb = 0; nb < NB; nb++)
                vr[nb] = fmaf(S[EO_H + nb * TWO_D + k], wv, vr[nb]);
        }
        #pragma unroll
        for (int nb = 0; nb < NB; nb++) S[EO_VAR + nb * D + d] = softplus_f(vr[nb]);
    }
    __syncthreads();

    // ---- z, KL ----
    float term[NB];
    #pragma unroll
    for (int nb = 0; nb < NB; nb++) term[nb] = 0.f;
    if (tid < D) {
        int d = tid;
        float eps = epsilon[d];
        #pragma unroll
        for (int nb = 0; nb < NB; nb++) {
            int b = b0 + nb;
            float m = S[EO_MEAN + nb * D + d];
            float v = S[EO_VAR + nb * D + d];
            float z = m + expf(0.5f * v) * eps;
            g_z[b * D + d] = z;
            float zn = __shfl_down_sync(0xffffffffu, z, 1);
            if (!(d & 1)) {
                __half2 hz = __floats2half2_rn(z, zn);
                g_zh2[(b * D + d) >> 1] = *(unsigned*)&hz;
            }
            float pm = prior_means[cid_s[nb] * D + d];
            float pv = softplus_f(prior_vars[cid_s[nb] * D + d]);
            float diff = pm - m;
            term[nb] = v / pv + diff * diff / pv - 1.f + logf(pv) - logf(v);
        }
    }
    #pragma unroll
    for (int nb = 0; nb < NB; nb++) {
        float t = term[nb];
        #pragma unroll
        for (int o = 16; o; o >>= 1) t += __shfl_xor_sync(0xffffffffu, t, o);
        if (tid < D && (tid & 31) == 0) red_s[nb][tid >> 5] = t;
    }
    __syncthreads();
    if (tid < NB) {
        float s = red_s[tid][0] + red_s[tid][1] + red_s[tid][2] + red_s[tid][3];
        g_kl[b0 + tid] = 0.5f * s;
    }
}

// ---------------- kernel 2: fp16 mma.sync vocab GEMM + fused softmax partials ----
__global__ void __launch_bounds__(256, 2) vocab_kernel(
    const float* __restrict__ Wv, const float* __restrict__ bvoc)
{
    __shared__ unsigned Ws[2 * WS_BUF];

    const int tid  = threadIdx.x;
    const int lane = tid & 31;
    const int w    = tid >> 5;
    const int g    = lane >> 2;
    const int cg   = lane & 3;
    const int v0   = blockIdx.x * N_CTA;
    const int b0   = blockIdx.y * M_CTA;

    const unsigned* zh0 = g_zh2 + (b0 + w * 16 + g) * (D / 2);
    const unsigned* zh1 = zh0 + 8 * (D / 2);

    const int n_f  = tid & 127;
    const int k2b  = tid >> 7;
    const int vf   = v0 + n_f;
    const bool okf = (vf < V);
    const float* wp = Wv + (okf ? vf : 0);

    float acc[16][4];
    #pragma unroll
    for (int t = 0; t < 16; t++)
        #pragma unroll
        for (int i = 0; i < 4; i++) acc[t][i] = 0.f;

    float plo[8], phi[8];
    #define LOADREGS(K0) do {                                                 \
        _Pragma("unroll")                                                     \
        for (int i = 0; i < 8; i++) {                                         \
            int kk = (K0) + 2 * (k2b + 2 * i);                                \
            plo[i] = okf ? wp[kk * V] : 0.f;                                  \
            phi[i] = okf ? wp[(kk + 1) * V] : 0.f;                            \
        } } while (0)
    #define STOREREGS(BUF) do {                                               \
        _Pragma("unroll")                                                     \
        for (int i = 0; i < 8; i++) {                                         \
            __half2 hv = __floats2half2_rn(plo[i], phi[i]);                   \
            (BUF)[(k2b + 2 * i) * WS_STRIDE + n_f] = *(unsigned*)&hv;         \
        } } while (0)

    LOADREGS(0);
    #pragma unroll
    for (int it = 0; it < 4; it++) {
        unsigned* buf = Ws + (it & 1) * WS_BUF;
        STOREREGS(buf);
        __syncthreads();
        if (it < 3) LOADREGS((it + 1) * KT);

        const int k0 = it * KT;
        #pragma unroll
        for (int ks = 0; ks < KT; ks += 16) {
            const int kh = (k0 + ks) >> 1;
            unsigned a0 = zh0[kh + cg];
            unsigned a1 = zh1[kh + cg];
            unsigned a2 = zh0[kh + cg + 4];
            unsigned a3 = zh1[kh + cg + 4];
            const unsigned* wsb0 = buf + ((ks >> 1) + cg) * WS_STRIDE + g;
            const unsigned* wsb1 = wsb0 + 4 * WS_STRIDE;
            #pragma unroll
            for (int t = 0; t < 16; t++)
                mma_f16(acc[t], a0, a1, a2, a3, wsb0[t * 8], wsb1[t * 8]);
        }
    }
    #undef LOADREGS
    #undef STOREREGS

    const int chunk = blockIdx.x;
    float m0 = -INFINITY, m1 = -INFINITY;
    #pragma unroll
    for (int t = 0; t < 16; t++) {
        int n = t * 8 + 2 * cg;
        bool ok0 = (v0 + n) < V;
        bool ok1 = (v0 + n + 1) < V;
        float bv0 = ok0 ? bvoc[v0 + n] : 0.f;
        float bv1 = ok1 ? bvoc[v0 + n + 1] : 0.f;
        acc[t][0] = ok0 ? acc[t][0] + bv0 : -INFINITY;
        acc[t][1] = ok1 ? acc[t][1] + bv1 : -INFINITY;
        acc[t][2] = ok0 ? acc[t][2] + bv0 : -INFINITY;
        acc[t][3] = ok1 ? acc[t][3] + bv1 : -INFINITY;
        m0 = fmaxf(m0, fmaxf(acc[t][0], acc[t][1]));
        m1 = fmaxf(m1, fmaxf(acc[t][2], acc[t][3]));
    }
    #pragma unroll
    for (int o = 1; o <= 2; o <<= 1) {
        m0 = fmaxf(m0, __shfl_xor_sync(0xffffffffu, m0, o));
        m1 = fmaxf(m1, __shfl_xor_sync(0xffffffffu, m1, o));
    }
    float s0 = 0.f, s1 = 0.f;
    #pragma unroll
    for (int t = 0; t < 16; t++) {
        s0 += __expf(acc[t][0] - m0) + __expf(acc[t][1] - m0);
        s1 += __expf(acc[t][2] - m1) + __expf(acc[t][3] - m1);
    }
    #pragma unroll
    for (int o = 1; o <= 2; o <<= 1) {
        s0 += __shfl_xor_sync(0xffffffffu, s0, o);
        s1 += __shfl_xor_sync(0xffffffffu, s1, o);
    }
    if (cg == 0) {
        int r0 = b0 + w * 16 + g;
        g_pmax[r0 * NCHUNK + chunk] = m0;
        g_psum[r0 * NCHUNK + chunk] = s0;
        g_pmax[(r0 + 8) * NCHUNK + chunk] = m1;
        g_psum[(r0 + 8) * NCHUNK + chunk] = s1;
    }
}

// ---------------- kernel 3: logsumexp combine + context gather + fused mean ----
__global__ void __launch_bounds__(128) finalize_rows(
    const float* __restrict__ Wv, const float* __restrict__ bvoc,
    const int* __restrict__ context_ids, float* __restrict__ out)
{
    __shared__ long long blk_s[4];

    const int warp = threadIdx.x >> 5;
    const int lane = threadIdx.x & 31;
    const int b = blockIdx.x * 4 + warp;

    float m = -INFINITY, s = 0.f;
    for (int ch = lane; ch < NCHUNK; ch += 32) {
        float m2 = g_pmax[b * NCHUNK + ch];
        float s2 = g_psum[b * NCHUNK + ch];
        if (m2 > m) { s = s * __expf(m - m2) + s2; m = m2; }
        else        { s += s2 * __expf(m2 - m); }
    }
    #pragma unroll
    for (int o = 16; o; o >>= 1) {
        float m2 = __shfl_xor_sync(0xffffffffu, m, o);
        float s2 = __shfl_xor_sync(0xffffffffu, s, o);
        if (m2 > m) { s = s * __expf(m - m2) + s2; m = m2; }
        else        { s += s2 * __expf(m2 - m); }
    }
    float lse = m + logf(s);

    float zr[4];
    #pragma unroll
    for (int t = 0; t < 4; t++) zr[t] = g_z[b * D + lane + 32 * t];

    float rec = 0.f;
    #pragma unroll
    for (int c = 0; c < C; c++) {
        int v = context_ids[b * C + c];
        float p = 0.f;
        #pragma unroll
        for (int t = 0; t < 4; t++)
            p = fmaf(zr[t], Wv[(lane + 32 * t) * V + v], p);
        #pragma unroll
        for (int o = 16; o; o >>= 1) p += __shfl_xor_sync(0xffffffffu, p, o);
        rec += p + bvoc[v] - lse;
    }

    if (lane == 0) {
        float val = rec - g_kl[b];
        blk_s[warp] = __double2ll_rn((double)val * 4294967296.0);
    }
    __syncthreads();
    if (threadIdx.x == 0) {
        long long bs = blk_s[0] + blk_s[1] + blk_s[2] + blk_s[3];
        atomicAdd((unsigned long long*)&g_acc, (unsigned long long)bs);
        __threadfence();
        unsigned int done = atomicAdd(&g_done, 1u);
        if (done == FIN_BLOCKS - 1) {
            long long tot = *(volatile long long*)&g_acc;
            out[0] = (float)((double)tot * (1.0 / 4294967296.0) * (1.0 / (double)B));
        }
    }
}

// ---------------- launch ----------------
extern "C" void kernel_launch(void* const* d_in, const int* in_sizes, int n_in,
                              void* d_out, int out_size)
{
    const int*   center_id   = (const int*)d_in[0];
    const int*   context_ids = (const int*)d_in[1];
    const float* epsilon     = (const float*)d_in[2];
    const float* emb         = (const float*)d_in[3];
    const float* prior_means = (const float*)d_in[4];
    const float* prior_vars  = (const float*)d_in[5];
    const float* W_enc       = (const float*)d_in[6];
    const float* b_enc       = (const float*)d_in[7];
    const float* W_mean      = (const float*)d_in[8];
    const float* b_mean      = (const float*)d_in[9];
    const float* W_var       = (const float*)d_in[10];
    const float* b_var       = (const float*)d_in[11];
    const float* W_vocab     = (const float*)d_in[12];
    const float* b_vocab     = (const float*)d_in[13];
    float* out = (float*)d_out;

    encoder_kernel<<<B / NB, 256>>>(center_id, context_ids, epsilon, emb,
                                    prior_means, prior_vars,
                                    W_enc, b_enc, W_mean, b_mean, W_var, b_var);

    dim3 grid2(NCHUNK, B / M_CTA);
    vocab_kernel<<<grid2, 256>>>(W_vocab, b_vocab);

    finalize_rows<<<FIN_BLOCKS, 128>>>(W_vocab, b_vocab, context_ids, out);
}